// round 1
// baseline (speedup 1.0000x reference)
#include <cuda_runtime.h>

// Gaussian splatting: N=50000 gaussians -> 256^3 fp32 volume.
// Separable exp: per-gaussian only <=48 expf; inner loop is pure multiply + RED.
// One warp per gaussian; z mapped to low 16 lanes for coalesced atomics.

#define NVOX (256 * 256 * 256)
#define WARPS_PER_BLOCK 8
#define THREADS (WARPS_PER_BLOCK * 32)

__global__ void splat_kernel(const float* __restrict__ centers,
                             const float* __restrict__ sigmas,
                             const float* __restrict__ intensities,
                             float* __restrict__ out,
                             int n) {
    const int gwarp = (blockIdx.x * blockDim.x + threadIdx.x) >> 5;
    const int lane  = threadIdx.x & 31;
    const int wloc  = threadIdx.x >> 5;
    if (gwarp >= n) return;

    __shared__ float sh[WARPS_PER_BLOCK][3][16];

    const float cx = centers[3 * gwarp + 0];
    const float cy = centers[3 * gwarp + 1];
    const float cz = centers[3 * gwarp + 2];
    const float sig = sigmas[gwarp];
    const float inten = intensities[gwarp];

    const float cut = 3.0f * sig * 255.0f;
    const float inv2s2 = 0.5f / (sig * sig);

    float c3[3];
    c3[0] = cx; c3[1] = cy; c3[2] = cz;

    int mn[3], mx[3];
#pragma unroll
    for (int a = 0; a < 3; a++) {
        float cv = c3[a] * 255.0f;
        mn[a] = (int)floorf(fmaxf(cv - cut, 0.0f));
        mx[a] = (int)fminf(floorf(fminf(cv + cut, 255.0f)) + 1.0f, 256.0f);
    }

    // Per-axis exp tables: 48 entries, computed by 32 lanes (lane, lane+32).
#pragma unroll
    for (int e = lane; e < 48; e += 32) {
        int a = e >> 4;
        int i = e & 15;
        int gi = mn[a] + i;
        float v = 0.0f;
        if (gi < mx[a]) {
            float d = (float)gi / 255.0f - c3[a];
            v = expf(-d * d * inv2s2);
            if (a == 2) v *= inten;
        }
        sh[wloc][a][i] = v;
    }
    __syncwarp();

    const int bx = mx[0] - mn[0];
    const int by = mx[1] - mn[1];
    const int bz = mx[2] - mn[2];
    const int npairs = bx * by;

    const int k = lane & 15;        // z offset within tile
    const int psub = lane >> 4;     // which of the 2 rows this half-warp handles
    const int mz = mn[2];

    for (int p0 = 0; p0 < npairs; p0 += 2) {
        int p = p0 + psub;
        if (p < npairs && k < bz) {
            int i = p / by;
            int j = p - i * by;
            float v = sh[wloc][0][i] * sh[wloc][1][j] * sh[wloc][2][k];
            int addr = (mn[0] + i) * 65536 + (mn[1] + j) * 256 + mz + k;
            atomicAdd(&out[addr], v);
        }
    }
}

extern "C" void kernel_launch(void* const* d_in, const int* in_sizes, int n_in,
                              void* d_out, int out_size) {
    const float* centers = (const float*)d_in[0];
    const float* sigmas = (const float*)d_in[1];
    const float* intensities = (const float*)d_in[2];
    float* out = (float*)d_out;
    const int n = in_sizes[1];  // number of gaussians

    // Output is poisoned before timing; zero it (memset node is graph-capturable).
    cudaMemsetAsync(out, 0, (size_t)NVOX * sizeof(float), 0);

    const int totalThreads = n * 32;
    const int blocks = (totalThreads + THREADS - 1) / THREADS;
    splat_kernel<<<blocks, THREADS>>>(centers, sigmas, intensities, out, n);
}

// round 2
// speedup vs baseline: 2.2704x; 2.2704x over previous
#include <cuda_runtime.h>

// Gaussian splatting: N=50000 gaussians -> 256^3 fp32 volume.
// Separable exp; one warp per gaussian. Lane packing: lane -> (dj, k) with
// k = z offset, dj = row within a group of rpi = 32/bz rows handled per RED.
// No integer division in the hot loop.

#define NVOX (256 * 256 * 256)
#define WARPS_PER_BLOCK 8
#define THREADS (WARPS_PER_BLOCK * 32)

__global__ void __launch_bounds__(THREADS) splat_kernel(
        const float* __restrict__ centers,
        const float* __restrict__ sigmas,
        const float* __restrict__ intensities,
        float* __restrict__ out,
        int n) {
    const int gwarp = blockIdx.x * WARPS_PER_BLOCK + (threadIdx.x >> 5);
    const int lane  = threadIdx.x & 31;
    const int wloc  = threadIdx.x >> 5;
    if (gwarp >= n) return;

    __shared__ float shx[WARPS_PER_BLOCK][16];
    __shared__ float shy[WARPS_PER_BLOCK][16];

    const float cx = __ldg(&centers[3 * gwarp + 0]);
    const float cy = __ldg(&centers[3 * gwarp + 1]);
    const float cz = __ldg(&centers[3 * gwarp + 2]);
    const float sig   = __ldg(&sigmas[gwarp]);
    const float inten = __ldg(&intensities[gwarp]);

    const float cut    = 3.0f * sig * 255.0f;
    const float inv2s2 = 0.5f / (sig * sig);

    float c3[3] = {cx, cy, cz};
    int mn[3], mx[3];
#pragma unroll
    for (int a = 0; a < 3; a++) {
        float cv = c3[a] * 255.0f;
        mn[a] = (int)floorf(fmaxf(cv - cut, 0.0f));
        mx[a] = (int)fminf(floorf(fminf(cv + cut, 255.0f)) + 1.0f, 256.0f);
    }
    const int bx = mx[0] - mn[0];
    const int by = mx[1] - mn[1];
    const int bz = mx[2] - mn[2];

    // Build x/y exp tables in shared: lanes 0..15 -> x, 16..31 -> y.
    {
        int a  = lane >> 4;          // 0 = x, 1 = y
        int i  = lane & 15;
        int gi = mn[a] + i;
        float v = 0.0f;
        int hi = (a == 0) ? mx[0] : mx[1];
        if (gi < hi) {
            float d = (float)gi / 255.0f - c3[a];
            v = expf(-d * d * inv2s2);
        }
        if (a == 0) shx[wloc][i] = v; else shy[wloc][i] = v;
    }

    // Lane mapping: dj = lane / bz, k = lane % bz  (one division per gaussian).
    const int dj  = lane / bz;
    const int k   = lane - dj * bz;
    const int rpi = 32 / bz;             // rows per RED instruction
    const bool lane_on = (dj < rpi);

    // Per-lane z factor (intensity folded in).
    float w;
    {
        float d = (float)(mn[2] + k) / 255.0f - cz;
        w = inten * expf(-d * d * inv2s2);
    }
    __syncwarp();

    // Per-lane base address for (i=0, j=dj, z=k).
    int base = mn[0] * 65536 + (mn[1] + dj) * 256 + mn[2] + k;
    const int jstep = rpi * 256;

    for (int i = 0; i < bx; i++) {
        const float vxw = shx[wloc][i] * w;
        int addr = base;
        for (int j = dj; j < by; j += rpi) {
            if (lane_on) {
                atomicAdd(&out[addr], vxw * shy[wloc][j]);
            }
            addr += jstep;
        }
        base += 65536;
    }
}

extern "C" void kernel_launch(void* const* d_in, const int* in_sizes, int n_in,
                              void* d_out, int out_size) {
    const float* centers = (const float*)d_in[0];
    const float* sigmas = (const float*)d_in[1];
    const float* intensities = (const float*)d_in[2];
    float* out = (float*)d_out;
    const int n = in_sizes[1];  // number of gaussians

    cudaMemsetAsync(out, 0, (size_t)NVOX * sizeof(float), 0);

    const int blocks = (n + WARPS_PER_BLOCK - 1) / WARPS_PER_BLOCK;
    splat_kernel<<<blocks, THREADS>>>(centers, sigmas, intensities, out, n);
}

// round 3
// speedup vs baseline: 2.4195x; 1.0657x over previous
#include <cuda_runtime.h>

// Gaussian splatting: N=50000 gaussians -> 256^3 fp32 volume.
// Separable exp; one warp per gaussian. Vectorized red.global.add.v2.f32:
// each lane owns a 2-voxel z-segment (8B aligned), rows packed across lanes.
// Padding lanes carry 0.0f (bitwise no-op on non-negative volume).

#define NVOX (256 * 256 * 256)
#define WARPS_PER_BLOCK 8
#define THREADS (WARPS_PER_BLOCK * 32)

__device__ __forceinline__ void red_add_v2(float* ptr, float a, float b) {
    asm volatile("red.global.add.v2.f32 [%0], {%1, %2};"
                 :: "l"(ptr), "f"(a), "f"(b) : "memory");
}

__global__ void __launch_bounds__(THREADS) splat_kernel(
        const float* __restrict__ centers,
        const float* __restrict__ sigmas,
        const float* __restrict__ intensities,
        float* __restrict__ out,
        int n) {
    const int gwarp = blockIdx.x * WARPS_PER_BLOCK + (threadIdx.x >> 5);
    const int lane  = threadIdx.x & 31;
    const int wloc  = threadIdx.x >> 5;
    if (gwarp >= n) return;

    __shared__ float shx[WARPS_PER_BLOCK][16];
    __shared__ float shy[WARPS_PER_BLOCK][16];

    const float cx = __ldg(&centers[3 * gwarp + 0]);
    const float cy = __ldg(&centers[3 * gwarp + 1]);
    const float cz = __ldg(&centers[3 * gwarp + 2]);
    const float sig   = __ldg(&sigmas[gwarp]);
    const float inten = __ldg(&intensities[gwarp]);

    const float cut    = 3.0f * sig * 255.0f;
    const float inv2s2 = 0.5f / (sig * sig);

    float c3[3] = {cx, cy, cz};
    int mn[3], mx[3];
#pragma unroll
    for (int a = 0; a < 3; a++) {
        float cv = c3[a] * 255.0f;
        mn[a] = (int)floorf(fmaxf(cv - cut, 0.0f));
        mx[a] = (int)fminf(floorf(fminf(cv + cut, 255.0f)) + 1.0f, 256.0f);
    }
    const int bx = mx[0] - mn[0];
    const int by = mx[1] - mn[1];

    // x/y exp tables: lanes 0..15 -> x, 16..31 -> y.
    {
        int a  = lane >> 4;
        int i  = lane & 15;
        int gi = mn[a] + i;
        float v = 0.0f;
        int hi = (a == 0) ? mx[0] : mx[1];
        if (gi < hi) {
            float d = (float)gi / 255.0f - c3[a];
            v = expf(-d * d * inv2s2);
        }
        if (a == 0) shx[wloc][i] = v; else shy[wloc][i] = v;
    }

    // z-axis: 8B-aligned vector span [zs, zs + 2*nvec), padded entries weight 0.
    const int zs   = mn[2] & ~1;
    const int nvec = (mx[2] - zs + 1) >> 1;      // ceil(span/2), in [2,8]
    const int dj   = lane / nvec;                // row within group
    const int kv   = lane - dj * nvec;           // vector index along z
    const int rpi  = 32 / nvec;                  // rows per RED instruction
    const bool lane_on = (dj < rpi);

    // Per-lane z weight pair, intensity folded in, zero outside [mn2, mx2).
    const int z0 = zs + 2 * kv;
    float w0 = 0.0f, w1 = 0.0f;
    if (z0 >= mn[2] && z0 < mx[2]) {
        float d = (float)z0 / 255.0f - cz;
        w0 = inten * expf(-d * d * inv2s2);
    }
    if (z0 + 1 >= mn[2] && z0 + 1 < mx[2]) {
        float d = (float)(z0 + 1) / 255.0f - cz;
        w1 = inten * expf(-d * d * inv2s2);
    }
    __syncwarp();

    int base = mn[0] * 65536 + (mn[1] + dj) * 256 + z0;
    const int jstep = rpi * 256;

    for (int i = 0; i < bx; i++) {
        const float vx = shx[wloc][i];
        int addr = base;
        for (int j = dj; j < by; j += rpi) {
            if (lane_on) {
                const float vxy = vx * shy[wloc][j];
                red_add_v2(&out[addr], vxy * w0, vxy * w1);
            }
            addr += jstep;
        }
        base += 65536;
    }
}

extern "C" void kernel_launch(void* const* d_in, const int* in_sizes, int n_in,
                              void* d_out, int out_size) {
    const float* centers = (const float*)d_in[0];
    const float* sigmas = (const float*)d_in[1];
    const float* intensities = (const float*)d_in[2];
    float* out = (float*)d_out;
    const int n = in_sizes[1];

    cudaMemsetAsync(out, 0, (size_t)NVOX * sizeof(float), 0);

    const int blocks = (n + WARPS_PER_BLOCK - 1) / WARPS_PER_BLOCK;
    splat_kernel<<<blocks, THREADS>>>(centers, sigmas, intensities, out, n);
}

// round 4
// speedup vs baseline: 2.4744x; 1.0227x over previous
#include <cuda_runtime.h>

// Gaussian splatting: N=50000 gaussians -> 256^3 fp32 volume.
// Separable exp; one warp per gaussian; red.global.add.v2.f32.
// R4: register-cached row weights, unrolled inner loop, magic div,
// zero-weight lanes predicated off (no padding sector traffic).

#define NVOX (256 * 256 * 256)
#define WARPS_PER_BLOCK 8
#define THREADS (WARPS_PER_BLOCK * 32)

__device__ __forceinline__ void red_add_v2(float* ptr, float a, float b) {
    asm volatile("red.global.add.v2.f32 [%0], {%1, %2};"
                 :: "l"(ptr), "f"(a), "f"(b) : "memory");
}

__global__ void __launch_bounds__(THREADS) splat_kernel(
        const float* __restrict__ centers,
        const float* __restrict__ sigmas,
        const float* __restrict__ intensities,
        float* __restrict__ out,
        int n) {
    const int gwarp = blockIdx.x * WARPS_PER_BLOCK + (threadIdx.x >> 5);
    const int lane  = threadIdx.x & 31;
    const int wloc  = threadIdx.x >> 5;
    if (gwarp >= n) return;

    __shared__ float shx[WARPS_PER_BLOCK][16];
    __shared__ float shy[WARPS_PER_BLOCK][16];

    const float cx = __ldg(&centers[3 * gwarp + 0]);
    const float cy = __ldg(&centers[3 * gwarp + 1]);
    const float cz = __ldg(&centers[3 * gwarp + 2]);
    const float sig   = __ldg(&sigmas[gwarp]);
    const float inten = __ldg(&intensities[gwarp]);

    const float cut    = 3.0f * sig * 255.0f;
    const float inv2s2 = 0.5f / (sig * sig);

    float c3[3] = {cx, cy, cz};
    int mn[3], mx[3];
#pragma unroll
    for (int a = 0; a < 3; a++) {
        float cv = c3[a] * 255.0f;
        mn[a] = (int)floorf(fmaxf(cv - cut, 0.0f));
        mx[a] = (int)fminf(floorf(fminf(cv + cut, 255.0f)) + 1.0f, 256.0f);
    }
    const int bx = mx[0] - mn[0];
    const int by = mx[1] - mn[1];

    // x/y exp tables: lanes 0..15 -> x, 16..31 -> y.
    {
        int a  = lane >> 4;
        int i  = lane & 15;
        int gi = mn[a] + i;
        float v = 0.0f;
        int hi = (a == 0) ? mx[0] : mx[1];
        if (gi < hi) {
            float d = (float)gi / 255.0f - c3[a];
            v = expf(-d * d * inv2s2);
        }
        if (a == 0) shx[wloc][i] = v; else shy[wloc][i] = v;
    }

    // z-axis: 8B-aligned vector span, nvec in [1,8].
    const int zs   = mn[2] & ~1;
    const int nvec = (mx[2] - zs + 1) >> 1;
    const unsigned magic = 255u / (unsigned)nvec + 1u;   // exact floor div for lane<32
    const int dj   = (int)((lane * magic) >> 8);
    const int kv   = lane - dj * nvec;
    const int rpi  = 32 / nvec;                          // rows per RED
    const bool lane_on = (dj < rpi);

    // Per-lane z weight pair, intensity folded in.
    const int z0 = zs + 2 * kv;
    float w0 = 0.0f, w1 = 0.0f;
    if (z0 >= mn[2] && z0 < mx[2]) {
        float d = (float)z0 / 255.0f - cz;
        w0 = inten * expf(-d * d * inv2s2);
    }
    if (z0 + 1 >= mn[2] && z0 + 1 < mx[2]) {
        float d = (float)(z0 + 1) / 255.0f - cz;
        w1 = inten * expf(-d * d * inv2s2);
    }
    __syncwarp();

    // Precompute per-lane row weights for rows j = dj + m*rpi (m < M <= 4).
    const int M = (by + rpi - 1) / rpi;
    float zy0[4], zy1[4];
    bool  on[4];
#pragma unroll
    for (int m = 0; m < 4; m++) {
        int j = dj + m * rpi;
        bool v = lane_on && (j < by);
        float s = v ? shy[wloc][j < 16 ? j : 0] : 0.0f;
        zy0[m] = s * w0;
        zy1[m] = s * w1;
        on[m]  = v && ((w0 != 0.0f) | (w1 != 0.0f)) && (s != 0.0f);
    }

    int base = mn[0] * 65536 + (mn[1] + dj) * 256 + z0;
    const int jstep = rpi * 256;

    for (int i = 0; i < bx; i++) {
        const float vx = shx[wloc][i];
        int addr = base;
#pragma unroll
        for (int m = 0; m < 4; m++) {
            if (m < M) {
                if (on[m]) {
                    red_add_v2(&out[addr], vx * zy0[m], vx * zy1[m]);
                }
                addr += jstep;
            }
        }
        base += 65536;
    }
}

extern "C" void kernel_launch(void* const* d_in, const int* in_sizes, int n_in,
                              void* d_out, int out_size) {
    const float* centers = (const float*)d_in[0];
    const float* sigmas = (const float*)d_in[1];
    const float* intensities = (const float*)d_in[2];
    float* out = (float*)d_out;
    const int n = in_sizes[1];

    cudaMemsetAsync(out, 0, (size_t)NVOX * sizeof(float), 0);

    const int blocks = (n + WARPS_PER_BLOCK - 1) / WARPS_PER_BLOCK;
    splat_kernel<<<blocks, THREADS>>>(centers, sigmas, intensities, out, n);
}